// round 16
// baseline (speedup 1.0000x reference)
#include <cuda_runtime.h>
#include <cstdint>

#define B_  64
#define T_  2048
#define IN_ 64
#define H_  256
#define BT  (B_*T_)

#define ALPHA  0.2f
#define OMA    0.8f   // 1 - alpha

// Scratch for P = I @ W_in^T + b (padded by 2 steps; harmless).
__device__ float g_P[((size_t)BT + 2) * H_];

typedef unsigned long long u64;

__device__ __forceinline__ void ffma2(u64 &acc, u64 a, u64 b) {
    asm("fma.rn.f32x2 %0, %1, %2, %0;" : "+l"(acc) : "l"(a), "l"(b));
}
__device__ __forceinline__ float lo32(u64 v) { return __uint_as_float((unsigned)v); }
__device__ __forceinline__ float hi32(u64 v) { return __uint_as_float((unsigned)(v >> 32)); }

// Accurate tanh via MUFU-backed __expf (rel err ~2 ulp) — the version from the
// best measured rec_kernel.
__device__ __forceinline__ float tanh_acc(float x) {
    x = fminf(fmaxf(x, -30.f), 30.f);
    float e = __expf(2.f * x);
    return (e - 1.f) / (e + 1.f);
}

// ---------------------------------------------------------------------------
// Kernel 1: P[bt][h] = sum_k I[bt][k] * W_in[h][k] + b[h]
// 2 h-rows per thread (halved LDS bytes, proven R15) + 4 independent
// accumulator chains per row (chain depth 64 -> 16 FFMAs) to attack the
// measured issue=38% latency bound.
// ---------------------------------------------------------------------------
__global__ void __launch_bounds__(128) pre_kernel(const float* __restrict__ I,
                                                  const float* __restrict__ Win,
                                                  const float* __restrict__ bvec) {
    __shared__ float4 sI[16 * 16];   // 16 rows x 64 floats
    const int row0 = blockIdx.x * 16;
    const int tid  = threadIdx.x;

    const float4* I4 = (const float4*)(I + (size_t)row0 * IN_);
    sI[tid]       = I4[tid];
    sI[tid + 128] = I4[tid + 128];
    __syncthreads();

    const int h0 = tid;
    const int h1 = tid + 128;
    float4 w0[16], w1[16];
    const float4* W40 = (const float4*)(Win + h0 * IN_);
    const float4* W41 = (const float4*)(Win + h1 * IN_);
#pragma unroll
    for (int j = 0; j < 16; j++) { w0[j] = W40[j]; w1[j] = W41[j]; }
    const float bb0 = bvec[h0];
    const float bb1 = bvec[h1];

#pragma unroll 4
    for (int r = 0; r < 16; r++) {
        // 4 independent chains per h-row: chain depth 16 (was 64).
        float a00 = bb0, a01 = 0.f, a02 = 0.f, a03 = 0.f;
        float a10 = bb1, a11 = 0.f, a12 = 0.f, a13 = 0.f;
#pragma unroll
        for (int j = 0; j < 16; j++) {
            float4 iv = sI[r * 16 + j];   // broadcast, feeds BOTH h-rows
            a00 = fmaf(w0[j].x, iv.x, a00);
            a01 = fmaf(w0[j].y, iv.y, a01);
            a02 = fmaf(w0[j].z, iv.z, a02);
            a03 = fmaf(w0[j].w, iv.w, a03);
            a10 = fmaf(w1[j].x, iv.x, a10);
            a11 = fmaf(w1[j].y, iv.y, a11);
            a12 = fmaf(w1[j].z, iv.z, a12);
            a13 = fmaf(w1[j].w, iv.w, a13);
        }
        g_P[(size_t)(row0 + r) * H_ + h0] = (a00 + a01) + (a02 + a03);
        g_P[(size_t)(row0 + r) * H_ + h1] = (a10 + a11) + (a12 + a13);
    }
}

// ---------------------------------------------------------------------------
// Kernel 2: persistent recurrence — R1 body (best measured ~1796us) with ONE
// minimal change: 4 accumulator chains instead of 2, halving the serial FFMA2
// dependency depth per step (2x64 -> 4x32). Everything else identical.
// ---------------------------------------------------------------------------
__global__ void __launch_bounds__(256, 1) rec_kernel(const float* __restrict__ x0,
                                                     const float* __restrict__ Wrec,
                                                     float* __restrict__ out_u) {
    extern __shared__ float smem[];
    ulonglong2* wsm = (ulonglong2*)smem;          // [16][256] = 64 KB
    float* rbuf = smem + 16 * H_ * 4;             // 2 x 256 floats, 16B aligned

    const int b = blockIdx.x;
    const int h = threadIdx.x;

    // SMEM part of W: row h, float4 chunks 48..63  ->  wsm[j4][h]
    const float4* Wrow4 = (const float4*)(Wrec + h * H_);
#pragma unroll
    for (int j4 = 0; j4 < 16; j4++) {
        float4 v = Wrow4[48 + j4];
        wsm[j4 * H_ + h] = *(ulonglong2*)&v;
    }

    // Register part of W: 96 u64 = k pairs (0,1)..(190,191)
    u64 wr[96];
    const u64* Wrow2 = (const u64*)(Wrec + h * H_);
#pragma unroll
    for (int j = 0; j < 96; j++) wr[j] = Wrow2[j];

    float u = x0[b * H_ + h];
    const float* Pb = g_P + (size_t)b * T_ * H_;
    float* ub = out_u + (size_t)b * T_ * H_;

    float pv0 = __ldg(Pb + h);          // P[t]
    float pv1 = __ldg(Pb + H_ + h);     // P[t+1]
    __syncthreads();

    for (int t = 0; t < T_; t++) {
        float r = tanh_acc(u);
        float* rb = rbuf + (t & 1) * H_;
        rb[h] = r;
        __syncthreads();

        const ulonglong2* r16 = (const ulonglong2*)rb;
        u64 aA = 0ull, aB = 0ull, aC = 0ull, aD = 0ull;
#pragma unroll
        for (int j4 = 0; j4 < 24; j4++) {
            ulonglong2 rr = r16[j4];            // LDS.128 broadcast
            ffma2(aA, wr[2 * j4],     rr.x);
            ffma2(aB, wr[2 * j4 + 1], rr.y);
        }
#pragma unroll
        for (int j4 = 24; j4 < 48; j4++) {
            ulonglong2 rr = r16[j4];            // LDS.128 broadcast
            ffma2(aC, wr[2 * j4],     rr.x);
            ffma2(aD, wr[2 * j4 + 1], rr.y);
        }
#pragma unroll
        for (int j4 = 0; j4 < 16; j4++) {
            ulonglong2 rr = r16[48 + j4];       // LDS.128 broadcast
            ulonglong2 wv = wsm[j4 * H_ + h];   // LDS.128 conflict-free
            ffma2(aA, wv.x, rr.x);
            ffma2(aB, wv.y, rr.y);
        }

        float drive = ((lo32(aA) + hi32(aA)) + (lo32(aB) + hi32(aB)))
                    + ((lo32(aC) + hi32(aC)) + (lo32(aD) + hi32(aD))) + pv0;
        u = OMA * u + ALPHA * drive;
        ub[t * H_ + h] = u;                     // coalesced store

        pv0 = pv1;
        pv1 = (t + 2 < T_) ? __ldg(Pb + (size_t)(t + 2) * H_ + h) : 0.f;
    }
}

// ---------------------------------------------------------------------------
// Kernel 3: y[bt][j] = sum_h u[bt][h]*Wout[j][h] + bout[j].  Warp per row.
// ---------------------------------------------------------------------------
__global__ void __launch_bounds__(256) y_kernel(const float* __restrict__ u,
                                                const float* __restrict__ Wout,
                                                const float* __restrict__ bout,
                                                float* __restrict__ y) {
    const int warp = threadIdx.x >> 5;
    const int lane = threadIdx.x & 31;
    const size_t row = (size_t)blockIdx.x * 8 + warp;

    const float4* u4  = (const float4*)(u + row * H_);
    const float4* w04 = (const float4*)(Wout);
    const float4* w14 = (const float4*)(Wout + H_);

    float s0 = 0.f, s1 = 0.f;
#pragma unroll
    for (int j = 0; j < 2; j++) {
        int idx = j * 32 + lane;                // consecutive lanes -> coalesced
        float4 a  = u4[idx];
        float4 w0 = w04[idx];
        float4 w1 = w14[idx];
        s0 += a.x * w0.x + a.y * w0.y + a.z * w0.z + a.w * w0.w;
        s1 += a.x * w1.x + a.y * w1.y + a.z * w1.z + a.w * w1.w;
    }
#pragma unroll
    for (int off = 16; off; off >>= 1) {
        s0 += __shfl_xor_sync(0xffffffffu, s0, off);
        s1 += __shfl_xor_sync(0xffffffffu, s1, off);
    }
    if (lane == 0) {
        y[row * 2 + 0] = s0 + bout[0];
        y[row * 2 + 1] = s1 + bout[1];
    }
}

// ---------------------------------------------------------------------------
// Launch. Inputs (metadata order): x0, I, W_in, W_rec, b, Wout, bout.
// Output: [u (B*T*H) | y (B*T*2)] concatenated.
// ---------------------------------------------------------------------------
extern "C" void kernel_launch(void* const* d_in, const int* in_sizes, int n_in,
                              void* d_out, int out_size) {
    const float* x0   = (const float*)d_in[0];
    const float* I    = (const float*)d_in[1];
    const float* Win  = (const float*)d_in[2];
    const float* Wrec = (const float*)d_in[3];
    const float* bv   = (const float*)d_in[4];
    const float* Wout = (const float*)d_in[5];
    const float* bout = (const float*)d_in[6];

    float* out_u = (float*)d_out;
    float* out_y = out_u + (size_t)BT * H_;

    const int smem_bytes = (16 * H_ * 4 + 2 * H_) * (int)sizeof(float);  // 67584
    cudaFuncSetAttribute(rec_kernel, cudaFuncAttributeMaxDynamicSharedMemorySize,
                         smem_bytes);

    pre_kernel<<<BT / 16, 128>>>(I, Win, bv);
    rec_kernel<<<B_, 256, smem_bytes>>>(x0, Wrec, out_u);
    y_kernel<<<BT / 8, 256>>>(out_u, Wout, bout, out_y);
}